// round 11
// baseline (speedup 1.0000x reference)
#include <cuda_runtime.h>
#include <cuda_bf16.h>
#include <mma.h>
#include <math.h>

typedef unsigned int u32;
typedef unsigned long long u64;
using namespace nvcuda;

#define G 2
#define NN 50000
#define NE 800000
#define M_NODES (G * NN)          // 100000
#define SCAN_BLK 1024
#define NBLK ((M_NODES + SCAN_BLK - 1) / SCAN_BLK)   // 98

// ---------------- scratch (device globals) ----------------
__device__ float          g_h1[(size_t)G * NN * 256];   // layer1 transformed (f32)
__device__ float          g_h2[(size_t)G * NN * 128];   // layer2 transformed (f32)
__device__ __nv_bfloat16  g_xhi[(size_t)G * NN * 128];  // x split
__device__ __nv_bfloat16  g_xlo[(size_t)G * NN * 128];
__device__ __nv_bfloat16  g_a1hi[(size_t)G * NN * 256]; // layer1 output split (GEMM2 input)
__device__ __nv_bfloat16  g_a1lo[(size_t)G * NN * 256];
__device__ __nv_bfloat16  g_w1hi[G * 128 * 256];        // W1 split, native [K][M]
__device__ __nv_bfloat16  g_w1lo[G * 128 * 256];
__device__ __nv_bfloat16  g_w2hi[G * 256 * 128];        // W2 split, native [K][M]
__device__ __nv_bfloat16  g_w2lo[G * 256 * 128];
__device__ float          g_als[G * NN * 4];
__device__ float          g_ald[G * NN * 4];
__device__ int            g_cnt[M_NODES];
__device__ int            g_rowptr[M_NODES + 1];
__device__ int            g_fill[M_NODES];
__device__ int            g_col[G * NE];
__device__ int            g_bsum[256];
__device__ int            g_bpre[256];

// ---------------- WMMA GEMM: O[g][N][M] = A[g][N][K] @ W[g][K][M], bf16x3, f32 accum ----------
// block 128x128, BK=32, 8 warps each 32x64. A double-buffered in smem (register-staged);
// B (weights) loaded as fragments straight from global — L1/L2 resident, no staging.
#define AS_LD 40              // A smem row stride (elements), pad vs bank conflicts

template <int K, int M>
__global__ void __launch_bounds__(256, 2) gemm_wmma_kernel(
    const __nv_bfloat16* __restrict__ Ahi, const __nv_bfloat16* __restrict__ Alo,
    const __nv_bfloat16* __restrict__ Bhi, const __nv_bfloat16* __restrict__ Blo,
    float* __restrict__ O) {
    __shared__ __nv_bfloat16 smA[2][2][128 * AS_LD];  // [buf][hi/lo][row*AS_LD + k]
    const int g = blockIdx.z;
    const int row0 = blockIdx.x * 128;
    const int col0 = blockIdx.y * 128;
    const int tid = threadIdx.x;
    const int wid = tid >> 5;
    const int wm = (wid & 3) * 32;        // warp row offset in tile
    const int wn = (wid >> 2) * 64;       // warp col offset in tile

    const __nv_bfloat16* Ah = Ahi + (size_t)g * NN * K;
    const __nv_bfloat16* Al = Alo + (size_t)g * NN * K;
    const __nv_bfloat16* Bh = Bhi + (size_t)g * K * M;
    const __nv_bfloat16* Bl = Blo + (size_t)g * K * M;

    // A staging: 128x32 tile = 512 uint4 per hi/lo buffer (2 per thread)
    const int ar0 = tid >> 2, ac0 = (tid & 3);
    const int ar1 = (tid + 256) >> 2, ac1 = ((tid + 256) & 3);

    wmma::fragment<wmma::accumulator, 16, 16, 16, float> acc[2][4];
#pragma unroll
    for (int i = 0; i < 2; i++)
#pragma unroll
        for (int n = 0; n < 4; n++) wmma::fill_fragment(acc[i][n], 0.f);

    uint4 rah0, rah1, ral0, ral1;

    const int NSTAGE = K / 32;
    // prologue: stage 0
    {
        rah0 = make_uint4(0, 0, 0, 0); ral0 = rah0; rah1 = rah0; ral1 = rah0;
        if (row0 + ar0 < NN) {
            size_t o = (size_t)(row0 + ar0) * K + ac0 * 8;
            rah0 = *(const uint4*)(Ah + o); ral0 = *(const uint4*)(Al + o);
        }
        if (row0 + ar1 < NN) {
            size_t o = (size_t)(row0 + ar1) * K + ac1 * 8;
            rah1 = *(const uint4*)(Ah + o); ral1 = *(const uint4*)(Al + o);
        }
        *(uint4*)((char*)smA[0][0] + ar0 * (AS_LD * 2) + ac0 * 16) = rah0;
        *(uint4*)((char*)smA[0][0] + ar1 * (AS_LD * 2) + ac1 * 16) = rah1;
        *(uint4*)((char*)smA[0][1] + ar0 * (AS_LD * 2) + ac0 * 16) = ral0;
        *(uint4*)((char*)smA[0][1] + ar1 * (AS_LD * 2) + ac1 * 16) = ral1;
    }
    __syncthreads();

    for (int st = 0; st < NSTAGE; st++) {
        const int buf = st & 1;
        const bool more = (st + 1) < NSTAGE;
        if (more) {
            const int ks = (st + 1) * 32;
            rah0 = make_uint4(0, 0, 0, 0); ral0 = rah0; rah1 = rah0; ral1 = rah0;
            if (row0 + ar0 < NN) {
                size_t o = (size_t)(row0 + ar0) * K + ks + ac0 * 8;
                rah0 = *(const uint4*)(Ah + o); ral0 = *(const uint4*)(Al + o);
            }
            if (row0 + ar1 < NN) {
                size_t o = (size_t)(row0 + ar1) * K + ks + ac1 * 8;
                rah1 = *(const uint4*)(Ah + o); ral1 = *(const uint4*)(Al + o);
            }
        }
        // compute 2 k16 steps from buf; B fragments straight from global (L1-hit)
        {
            const __nv_bfloat16* pAh = smA[buf][0];
            const __nv_bfloat16* pAl = smA[buf][1];
            const int ks0 = st * 32;
#pragma unroll
            for (int kk = 0; kk < 32; kk += 16) {
                wmma::fragment<wmma::matrix_a, 16, 16, 16, __nv_bfloat16, wmma::row_major> afh[2], afl[2];
#pragma unroll
                for (int i = 0; i < 2; i++) {
                    wmma::load_matrix_sync(afh[i], pAh + (wm + i * 16) * AS_LD + kk, AS_LD);
                    wmma::load_matrix_sync(afl[i], pAl + (wm + i * 16) * AS_LD + kk, AS_LD);
                }
                const __nv_bfloat16* pBh = Bh + (size_t)(ks0 + kk) * M + col0 + wn;
                const __nv_bfloat16* pBl = Bl + (size_t)(ks0 + kk) * M + col0 + wn;
#pragma unroll
                for (int n = 0; n < 4; n++) {
                    wmma::fragment<wmma::matrix_b, 16, 16, 16, __nv_bfloat16, wmma::row_major> bfh, bfl;
                    wmma::load_matrix_sync(bfh, pBh + n * 16, M);
                    wmma::load_matrix_sync(bfl, pBl + n * 16, M);
#pragma unroll
                    for (int i = 0; i < 2; i++) {
                        wmma::mma_sync(acc[i][n], afh[i], bfh, acc[i][n]);
                        wmma::mma_sync(acc[i][n], afh[i], bfl, acc[i][n]);
                        wmma::mma_sync(acc[i][n], afl[i], bfh, acc[i][n]);
                    }
                }
            }
        }
        if (more) {
            const int nb = (st + 1) & 1;
            *(uint4*)((char*)smA[nb][0] + ar0 * (AS_LD * 2) + ac0 * 16) = rah0;
            *(uint4*)((char*)smA[nb][0] + ar1 * (AS_LD * 2) + ac1 * 16) = rah1;
            *(uint4*)((char*)smA[nb][1] + ar0 * (AS_LD * 2) + ac0 * 16) = ral0;
            *(uint4*)((char*)smA[nb][1] + ar1 * (AS_LD * 2) + ac1 * 16) = ral1;
        }
        __syncthreads();
    }

    // epilogue: NN % 16 == 0, so per-frag row guard is exact
#pragma unroll
    for (int i = 0; i < 2; i++) {
        int rbase = row0 + wm + i * 16;
        if (rbase < NN) {
            float* op = O + (size_t)g * NN * M + (size_t)rbase * M + col0 + wn;
#pragma unroll
            for (int n = 0; n < 4; n++)
                wmma::store_matrix_sync(op + n * 16, acc[i][n], M, wmma::mem_row_major);
        }
    }
}

// ---------------- split conversion (elementwise; W kept in native [K][M] layout) --------------
__global__ void split_kernel(const float* __restrict__ in, __nv_bfloat16* __restrict__ hi,
                             __nv_bfloat16* __restrict__ lo, int n4) {
    int i = blockIdx.x * blockDim.x + threadIdx.x;
    if (i >= n4) return;
    float4 v = ((const float4*)in)[i];
    float a0 = v.x, a1 = v.y, a2 = v.z, a3 = v.w;
    __nv_bfloat16 h0 = __float2bfloat16(a0);
    __nv_bfloat16 h1 = __float2bfloat16(a1);
    __nv_bfloat16 h2 = __float2bfloat16(a2);
    __nv_bfloat16 h3 = __float2bfloat16(a3);
    hi[i * 4 + 0] = h0; hi[i * 4 + 1] = h1; hi[i * 4 + 2] = h2; hi[i * 4 + 3] = h3;
    lo[i * 4 + 0] = __float2bfloat16(a0 - __bfloat162float(h0));
    lo[i * 4 + 1] = __float2bfloat16(a1 - __bfloat162float(h1));
    lo[i * 4 + 2] = __float2bfloat16(a2 - __bfloat162float(h2));
    lo[i * 4 + 3] = __float2bfloat16(a3 - __bfloat162float(h3));
}

// ---------------- per-node attention logits ----------------
template <int H, int C>
__global__ void al_kernel(const float* __restrict__ hbuf, const float* __restrict__ a_src,
                          const float* __restrict__ a_dst, float* __restrict__ als,
                          float* __restrict__ ald) {
    int idx = blockIdx.x * blockDim.x + threadIdx.x;
    if (idx >= G * NN * H) return;
    int h = idx % H;
    int gn = idx / H;
    int g = gn / NN;
    const float* hp = hbuf + (size_t)gn * (H * C) + h * C;
    const float* as = a_src + (g * H + h) * C;
    const float* ad = a_dst + (g * H + h) * C;
    float s1 = 0.f, s2 = 0.f;
#pragma unroll
    for (int c = 0; c < C; c += 4) {
        float4 hv = *(const float4*)(hp + c);
        float4 av = *(const float4*)(as + c);
        float4 dv = *(const float4*)(ad + c);
        s1 += hv.x * av.x + hv.y * av.y + hv.z * av.z + hv.w * av.w;
        s2 += hv.x * dv.x + hv.y * dv.y + hv.z * dv.z + hv.w * dv.w;
    }
    als[idx] = s1;
    ald[idx] = s2;
}

// ---------------- CSR build ----------------
__global__ void csr_zero_kernel() {
    int i = blockIdx.x * blockDim.x + threadIdx.x;
    if (i < M_NODES) g_cnt[i] = 0;
}
__global__ void csr_hist_kernel(const int* __restrict__ ei) {
    int idx = blockIdx.x * blockDim.x + threadIdx.x;
    if (idx >= G * NE) return;
    int g = idx / NE, e = idx % NE;
    int dst = ei[(size_t)g * 2 * NE + NE + e];
    atomicAdd(&g_cnt[g * NN + dst], 1);
}
__global__ void csr_scanA_kernel() {
    __shared__ int sh[SCAN_BLK];
    int i = blockIdx.x * SCAN_BLK + threadIdx.x;
    int v = (i < M_NODES) ? g_cnt[i] : 0;
    sh[threadIdx.x] = v;
    __syncthreads();
#pragma unroll
    for (int off = 1; off < SCAN_BLK; off <<= 1) {
        int t = (threadIdx.x >= off) ? sh[threadIdx.x - off] : 0;
        __syncthreads();
        sh[threadIdx.x] += t;
        __syncthreads();
    }
    if (i < M_NODES) g_rowptr[i] = sh[threadIdx.x] - v;
    if (threadIdx.x == SCAN_BLK - 1) g_bsum[blockIdx.x] = sh[SCAN_BLK - 1];
}
__global__ void csr_scanB_kernel() {
    __shared__ int sh[128];
    int t = threadIdx.x;
    int v = (t < NBLK) ? g_bsum[t] : 0;
    sh[t] = v;
    __syncthreads();
#pragma unroll
    for (int off = 1; off < 128; off <<= 1) {
        int u = (t >= off) ? sh[t - off] : 0;
        __syncthreads();
        sh[t] += u;
        __syncthreads();
    }
    if (t < NBLK) g_bpre[t] = sh[t] - v;
    if (t == 127) g_rowptr[M_NODES] = sh[127];
}
__global__ void csr_scanC_kernel() {
    int i = blockIdx.x * blockDim.x + threadIdx.x;
    if (i >= M_NODES) return;
    int v = g_rowptr[i] + g_bpre[i / SCAN_BLK];
    g_rowptr[i] = v;
    g_fill[i] = v;
}
__global__ void csr_scatter_kernel(const int* __restrict__ ei) {
    int idx = blockIdx.x * blockDim.x + threadIdx.x;
    if (idx >= G * NE) return;
    int g = idx / NE, e = idx % NE;
    int src = ei[(size_t)g * 2 * NE + e];
    int dst = ei[(size_t)g * 2 * NE + NE + e];
    int pos = atomicAdd(&g_fill[g * NN + dst], 1);
    g_col[pos] = src;
}

// ---------------- fused online-softmax + aggregation + bias + ELU (warp per dst node) ----------
__device__ __forceinline__ float lrelu(float v) { return v > 0.f ? v : 0.2f * v; }

template <int H, int C, int SPLIT>
__global__ void node_agg_kernel(const float* __restrict__ als, const float* __restrict__ ald,
                                const float* __restrict__ hbuf, const float* __restrict__ bias,
                                float* __restrict__ outf, __nv_bfloat16* __restrict__ ohi,
                                __nv_bfloat16* __restrict__ olo) {
    int wid = (blockIdx.x * blockDim.x + threadIdx.x) >> 5;
    int lane = threadIdx.x & 31;
    if (wid >= M_NODES) return;
    int g = wid / NN;
    const int gbase = g * NN;

    int rbeg = g_rowptr[wid];
    int deg = g_rowptr[wid + 1] - rbeg;

    float aldh[H], m[H], s[H];
#pragma unroll
    for (int h = 0; h < H; h++) {
        aldh[h] = ald[wid * H + h];
        float selfv = lrelu(als[wid * H + h] + aldh[h]);
        m[h] = (lane == 0) ? selfv : -1e30f;
        s[h] = (lane == 0) ? 1.f : 0.f;
    }
    for (int i = lane; i < deg; i += 32) {
        int src = g_col[rbeg + i];
#pragma unroll
        for (int h = 0; h < H; h++) {
            float e = lrelu(als[(gbase + src) * H + h] + aldh[h]);
            float mn = fmaxf(m[h], e);
            s[h] = s[h] * __expf(m[h] - mn) + __expf(e - mn);
            m[h] = mn;
        }
    }
#pragma unroll
    for (int h = 0; h < H; h++) {
#pragma unroll
        for (int off = 16; off > 0; off >>= 1) {
            float mo = __shfl_xor_sync(0xFFFFFFFFu, m[h], off);
            float so = __shfl_xor_sync(0xFFFFFFFFu, s[h], off);
            float mn = fmaxf(m[h], mo);
            s[h] = s[h] * __expf(m[h] - mn) + so * __expf(mo - mn);
            m[h] = mn;
        }
    }

    constexpr int F = H * C;
    constexpr int PER = F / 32;
    const int f0 = lane * PER;
    const int myh = f0 / C;
    const float inv_s = 1.f / s[myh];
    const float mymx = m[myh];
    const float myald = aldh[myh];

    float acc[PER];
    {
        float selfv = lrelu(als[wid * H + myh] + myald);
        float a_self = __expf(selfv - mymx) * inv_s;
        const float* hp = hbuf + (size_t)wid * F + f0;
#pragma unroll
        for (int c = 0; c < PER; c += 4) {
            float4 v = *(const float4*)(hp + c);
            acc[c + 0] = v.x * a_self;
            acc[c + 1] = v.y * a_self;
            acc[c + 2] = v.z * a_self;
            acc[c + 3] = v.w * a_self;
        }
    }
#pragma unroll 2
    for (int i = 0; i < deg; i++) {
        int src = g_col[rbeg + i];
        float alpha = __expf(lrelu(als[(gbase + src) * H + myh] + myald) - mymx) * inv_s;
        const float* hp = hbuf + (size_t)(gbase + src) * F + f0;
#pragma unroll
        for (int c = 0; c < PER; c += 4) {
            float4 v = *(const float4*)(hp + c);
            acc[c + 0] += v.x * alpha;
            acc[c + 1] += v.y * alpha;
            acc[c + 2] += v.z * alpha;
            acc[c + 3] += v.w * alpha;
        }
    }
    const float* bp = bias + g * F + f0;
    if (SPLIT) {
        __nv_bfloat16* hp2 = ohi + (size_t)wid * F + f0;
        __nv_bfloat16* lp2 = olo + (size_t)wid * F + f0;
#pragma unroll
        for (int c = 0; c < PER; c++) {
            float v = acc[c] + bp[c];
            v = v > 0.f ? v : expm1f(v);
            __nv_bfloat16 h = __float2bfloat16(v);
            hp2[c] = h;
            lp2[c] = __float2bfloat16(v - __bfloat162float(h));
        }
    } else {
        float* op = outf + (size_t)wid * F + f0;
#pragma unroll
        for (int c = 0; c < PER; c++) {
            float v = acc[c] + bp[c];
            op[c] = v > 0.f ? v : expm1f(v);
        }
    }
}

// ---------------- host ----------------
static inline int ceil_div(int a, int b) { return (a + b - 1) / b; }

extern "C" void kernel_launch(void* const* d_in, const int* in_sizes, int n_in,
                              void* d_out, int out_size) {
    const float* x   = (const float*)d_in[0];
    const int*   ei  = (const int*)d_in[1];
    const float* W1  = (const float*)d_in[2];
    const float* a1s = (const float*)d_in[3];
    const float* a1d = (const float*)d_in[4];
    const float* b1  = (const float*)d_in[5];
    const float* W2  = (const float*)d_in[6];
    const float* a2s = (const float*)d_in[7];
    const float* a2d = (const float*)d_in[8];
    const float* b2  = (const float*)d_in[9];
    float* out = (float*)d_out;

    float *h1, *h2, *als, *ald;
    __nv_bfloat16 *xhi, *xlo, *a1hi, *a1lo, *w1hi, *w1lo, *w2hi, *w2lo;
    cudaGetSymbolAddress((void**)&h1, g_h1);
    cudaGetSymbolAddress((void**)&h2, g_h2);
    cudaGetSymbolAddress((void**)&als, g_als);
    cudaGetSymbolAddress((void**)&ald, g_ald);
    cudaGetSymbolAddress((void**)&xhi, g_xhi);
    cudaGetSymbolAddress((void**)&xlo, g_xlo);
    cudaGetSymbolAddress((void**)&a1hi, g_a1hi);
    cudaGetSymbolAddress((void**)&a1lo, g_a1lo);
    cudaGetSymbolAddress((void**)&w1hi, g_w1hi);
    cudaGetSymbolAddress((void**)&w1lo, g_w1lo);
    cudaGetSymbolAddress((void**)&w2hi, g_w2hi);
    cudaGetSymbolAddress((void**)&w2lo, g_w2lo);

    const int TPB = 256;
    const int nrow_blocks = ceil_div(NN, 128);  // 391

    // conversions first, gemm1 as the 4th launch (ncu capture window)
    split_kernel<<<ceil_div(G * NN * 128 / 4, TPB), TPB>>>(x, xhi, xlo, G * NN * 128 / 4);
    split_kernel<<<ceil_div(G * 128 * 256 / 4, TPB), TPB>>>(W1, w1hi, w1lo, G * 128 * 256 / 4);
    split_kernel<<<ceil_div(G * 256 * 128 / 4, TPB), TPB>>>(W2, w2hi, w2lo, G * 256 * 128 / 4);
    gemm_wmma_kernel<128, 256><<<dim3(nrow_blocks, 2, G), TPB>>>(xhi, xlo, w1hi, w1lo, h1);

    // CSR build (shared by both layers)
    csr_zero_kernel<<<ceil_div(M_NODES, TPB), TPB>>>();
    csr_hist_kernel<<<ceil_div(G * NE, TPB), TPB>>>(ei);
    csr_scanA_kernel<<<NBLK, SCAN_BLK>>>();
    csr_scanB_kernel<<<1, 128>>>();
    csr_scanC_kernel<<<ceil_div(M_NODES, TPB), TPB>>>();
    csr_scatter_kernel<<<ceil_div(G * NE, TPB), TPB>>>(ei);

    // ---- Layer 1: heads=4, C=64 ----
    al_kernel<4, 64><<<ceil_div(G * NN * 4, TPB), TPB>>>(h1, a1s, a1d, als, ald);
    node_agg_kernel<4, 64, 1><<<ceil_div(M_NODES * 32, TPB), TPB>>>(als, ald, h1, b1,
                                                                    (float*)0, a1hi, a1lo);

    // ---- Layer 2: heads=1, C=128 ----
    gemm_wmma_kernel<256, 128><<<dim3(nrow_blocks, 1, G), TPB>>>(a1hi, a1lo, w2hi, w2lo, h2);
    al_kernel<1, 128><<<ceil_div(G * NN, TPB), TPB>>>(h2, a2s, a2d, als, ald);
    node_agg_kernel<1, 128, 0><<<ceil_div(M_NODES * 32, TPB), TPB>>>(als, ald, h2, b2,
                                                                     out, (__nv_bfloat16*)0,
                                                                     (__nv_bfloat16*)0);
}

// round 13
// speedup vs baseline: 1.2250x; 1.2250x over previous
#include <cuda_runtime.h>
#include <cuda_bf16.h>
#include <mma.h>
#include <math.h>

typedef unsigned int u32;
typedef unsigned long long u64;
using namespace nvcuda;

#define G 2
#define NN 50000
#define NE 800000
#define M_NODES (G * NN)          // 100000
#define SCAN_BLK 1024
#define NBLK ((M_NODES + SCAN_BLK - 1) / SCAN_BLK)   // 98

// ---------------- scratch (device globals) ----------------
__device__ float          g_h1[(size_t)G * NN * 256];   // layer1 transformed (f32)
__device__ float          g_h2[(size_t)G * NN * 128];   // layer2 transformed (f32)
__device__ __nv_bfloat16  g_xhi[(size_t)G * NN * 128];  // x split
__device__ __nv_bfloat16  g_xlo[(size_t)G * NN * 128];
__device__ __nv_bfloat16  g_a1hi[(size_t)G * NN * 256]; // layer1 output split (GEMM2 input)
__device__ __nv_bfloat16  g_a1lo[(size_t)G * NN * 256];
__device__ __nv_bfloat16  g_w1hi[G * 128 * 256];        // W1 split, native [K][M]
__device__ __nv_bfloat16  g_w1lo[G * 128 * 256];
__device__ __nv_bfloat16  g_w2hi[G * 256 * 128];        // W2 split, native [K][M]
__device__ __nv_bfloat16  g_w2lo[G * 256 * 128];
__device__ float          g_als[G * NN * 4];
__device__ float          g_ald[G * NN * 4];
__device__ int            g_cnt[M_NODES];
__device__ int            g_rowptr[M_NODES + 1];
__device__ int            g_fill[M_NODES];
__device__ int            g_col[G * NE];
__device__ int            g_bsum[256];
__device__ int            g_bpre[256];

// ---------------- WMMA GEMM: O[g][N][M] = A[g][N][K] @ W[g][K][M], bf16x3, f32 accum ----------
// block 128x128, BK=32, 8 warps each 32x64. A and B staged in double-buffered dynamic smem
// via cp.async (LDGSTS) with a 2-deep commit/wait pipeline.
#define AS_LD 40                    // A smem row stride (elements)
#define BS_LD 136                   // B smem row stride (elements)
#define ASZ (128 * AS_LD * 2)       // bytes per A hi/lo sub-buffer (10240)
#define BSZ (32 * BS_LD * 2)        // bytes per B hi/lo sub-buffer (8704)
#define STAGE_B (2 * ASZ + 2 * BSZ) // 37888
#define SMEM_TOT (2 * STAGE_B)      // 75776

__device__ __forceinline__ void cpa16(u32 dst, const void* src, int sz) {
    asm volatile("cp.async.cg.shared.global [%0], [%1], 16, %2;"
                 :: "r"(dst), "l"(src), "r"(sz) : "memory");
}

template <int K, int M>
__device__ __forceinline__ void gemm_issue_stage(
    char* sbase, const __nv_bfloat16* Ah, const __nv_bfloat16* Al,
    const __nv_bfloat16* Bh, const __nv_bfloat16* Bl,
    int row0, int col0, int ks, int tid) {
    const int ar0 = tid >> 2, ac0 = tid & 3;
    const int ar1 = ar0 + 64;
    const int bk0 = tid >> 4, bn0 = tid & 15;
    const int bk1 = bk0 + 16;
    u32 s = (u32)__cvta_generic_to_shared(sbase);
    int in0 = (row0 + ar0 < NN);
    int in1 = (row0 + ar1 < NN);
    size_t ao0 = (size_t)(in0 ? (row0 + ar0) : 0) * K + ks + ac0 * 8;
    size_t ao1 = (size_t)(in1 ? (row0 + ar1) : 0) * K + ks + ac0 * 8;
    cpa16(s + ar0 * (AS_LD * 2) + ac0 * 16, Ah + ao0, in0 ? 16 : 0);
    cpa16(s + ar1 * (AS_LD * 2) + ac0 * 16, Ah + ao1, in1 ? 16 : 0);
    cpa16(s + ASZ + ar0 * (AS_LD * 2) + ac0 * 16, Al + ao0, in0 ? 16 : 0);
    cpa16(s + ASZ + ar1 * (AS_LD * 2) + ac0 * 16, Al + ao1, in1 ? 16 : 0);
    size_t bo0 = (size_t)(ks + bk0) * M + col0 + bn0 * 8;
    size_t bo1 = (size_t)(ks + bk1) * M + col0 + bn0 * 8;
    cpa16(s + 2 * ASZ + bk0 * (BS_LD * 2) + bn0 * 16, Bh + bo0, 16);
    cpa16(s + 2 * ASZ + bk1 * (BS_LD * 2) + bn0 * 16, Bh + bo1, 16);
    cpa16(s + 2 * ASZ + BSZ + bk0 * (BS_LD * 2) + bn0 * 16, Bl + bo0, 16);
    cpa16(s + 2 * ASZ + BSZ + bk1 * (BS_LD * 2) + bn0 * 16, Bl + bo1, 16);
}

template <int K, int M>
__global__ void __launch_bounds__(256, 2) gemm_wmma_kernel(
    const __nv_bfloat16* __restrict__ Ahi, const __nv_bfloat16* __restrict__ Alo,
    const __nv_bfloat16* __restrict__ Bhi, const __nv_bfloat16* __restrict__ Blo,
    float* __restrict__ O) {
    extern __shared__ char sm[];
    const int g = blockIdx.z;
    const int row0 = blockIdx.x * 128;
    const int col0 = blockIdx.y * 128;
    const int tid = threadIdx.x;
    const int wid = tid >> 5;
    const int wm = (wid & 3) * 32;        // warp row offset in tile
    const int wn = (wid >> 2) * 64;       // warp col offset in tile

    const __nv_bfloat16* Ah = Ahi + (size_t)g * NN * K;
    const __nv_bfloat16* Al = Alo + (size_t)g * NN * K;
    const __nv_bfloat16* Bh = Bhi + (size_t)g * K * M;
    const __nv_bfloat16* Bl = Blo + (size_t)g * K * M;

    wmma::fragment<wmma::accumulator, 16, 16, 16, float> acc[2][4];
#pragma unroll
    for (int i = 0; i < 2; i++)
#pragma unroll
        for (int n = 0; n < 4; n++) wmma::fill_fragment(acc[i][n], 0.f);

    const int NSTAGE = K / 32;
    gemm_issue_stage<K, M>(sm, Ah, Al, Bh, Bl, row0, col0, 0, tid);
    asm volatile("cp.async.commit_group;" ::: "memory");
    gemm_issue_stage<K, M>(sm + STAGE_B, Ah, Al, Bh, Bl, row0, col0, 32, tid);
    asm volatile("cp.async.commit_group;" ::: "memory");

    for (int st = 0; st < NSTAGE; st++) {
        if (st + 1 < NSTAGE) {
            asm volatile("cp.async.wait_group 1;" ::: "memory");
        } else {
            asm volatile("cp.async.wait_group 0;" ::: "memory");
        }
        __syncthreads();
        {
            char* base = sm + (st & 1) * STAGE_B;
            const __nv_bfloat16* pAh = (const __nv_bfloat16*)(base);
            const __nv_bfloat16* pAl = (const __nv_bfloat16*)(base + ASZ);
            const __nv_bfloat16* pBh = (const __nv_bfloat16*)(base + 2 * ASZ);
            const __nv_bfloat16* pBl = (const __nv_bfloat16*)(base + 2 * ASZ + BSZ);
#pragma unroll
            for (int kk = 0; kk < 32; kk += 16) {
                wmma::fragment<wmma::matrix_a, 16, 16, 16, __nv_bfloat16, wmma::row_major> afh[2], afl[2];
#pragma unroll
                for (int i = 0; i < 2; i++) {
                    wmma::load_matrix_sync(afh[i], pAh + (wm + i * 16) * AS_LD + kk, AS_LD);
                    wmma::load_matrix_sync(afl[i], pAl + (wm + i * 16) * AS_LD + kk, AS_LD);
                }
#pragma unroll
                for (int n = 0; n < 4; n++) {
                    wmma::fragment<wmma::matrix_b, 16, 16, 16, __nv_bfloat16, wmma::row_major> bfh, bfl;
                    wmma::load_matrix_sync(bfh, pBh + kk * BS_LD + wn + n * 16, BS_LD);
                    wmma::load_matrix_sync(bfl, pBl + kk * BS_LD + wn + n * 16, BS_LD);
#pragma unroll
                    for (int i = 0; i < 2; i++) {
                        wmma::mma_sync(acc[i][n], afh[i], bfh, acc[i][n]);
                        wmma::mma_sync(acc[i][n], afh[i], bfl, acc[i][n]);
                        wmma::mma_sync(acc[i][n], afl[i], bfh, acc[i][n]);
                    }
                }
            }
        }
        if (st + 2 < NSTAGE) {
            __syncthreads();  // all warps done reading buf (st&1) before overwrite
            gemm_issue_stage<K, M>(sm + (st & 1) * STAGE_B, Ah, Al, Bh, Bl,
                                   row0, col0, (st + 2) * 32, tid);
            asm volatile("cp.async.commit_group;" ::: "memory");
        }
    }

    // epilogue: NN % 16 == 0, so per-frag row guard is exact
#pragma unroll
    for (int i = 0; i < 2; i++) {
        int rbase = row0 + wm + i * 16;
        if (rbase < NN) {
            float* op = O + (size_t)g * NN * M + (size_t)rbase * M + col0 + wn;
#pragma unroll
            for (int n = 0; n < 4; n++)
                wmma::store_matrix_sync(op + n * 16, acc[i][n], M, wmma::mem_row_major);
        }
    }
}

// ---------------- split conversion (elementwise; W kept in native [K][M] layout) --------------
__global__ void split_kernel(const float* __restrict__ in, __nv_bfloat16* __restrict__ hi,
                             __nv_bfloat16* __restrict__ lo, int n4) {
    int i = blockIdx.x * blockDim.x + threadIdx.x;
    if (i >= n4) return;
    float4 v = ((const float4*)in)[i];
    float a0 = v.x, a1 = v.y, a2 = v.z, a3 = v.w;
    __nv_bfloat16 h0 = __float2bfloat16(a0);
    __nv_bfloat16 h1 = __float2bfloat16(a1);
    __nv_bfloat16 h2 = __float2bfloat16(a2);
    __nv_bfloat16 h3 = __float2bfloat16(a3);
    hi[i * 4 + 0] = h0; hi[i * 4 + 1] = h1; hi[i * 4 + 2] = h2; hi[i * 4 + 3] = h3;
    lo[i * 4 + 0] = __float2bfloat16(a0 - __bfloat162float(h0));
    lo[i * 4 + 1] = __float2bfloat16(a1 - __bfloat162float(h1));
    lo[i * 4 + 2] = __float2bfloat16(a2 - __bfloat162float(h2));
    lo[i * 4 + 3] = __float2bfloat16(a3 - __bfloat162float(h3));
}

// ---------------- per-node attention logits ----------------
template <int H, int C>
__global__ void al_kernel(const float* __restrict__ hbuf, const float* __restrict__ a_src,
                          const float* __restrict__ a_dst, float* __restrict__ als,
                          float* __restrict__ ald) {
    int idx = blockIdx.x * blockDim.x + threadIdx.x;
    if (idx >= G * NN * H) return;
    int h = idx % H;
    int gn = idx / H;
    int g = gn / NN;
    const float* hp = hbuf + (size_t)gn * (H * C) + h * C;
    const float* as = a_src + (g * H + h) * C;
    const float* ad = a_dst + (g * H + h) * C;
    float s1 = 0.f, s2 = 0.f;
#pragma unroll
    for (int c = 0; c < C; c += 4) {
        float4 hv = *(const float4*)(hp + c);
        float4 av = *(const float4*)(as + c);
        float4 dv = *(const float4*)(ad + c);
        s1 += hv.x * av.x + hv.y * av.y + hv.z * av.z + hv.w * av.w;
        s2 += hv.x * dv.x + hv.y * dv.y + hv.z * dv.z + hv.w * dv.w;
    }
    als[idx] = s1;
    ald[idx] = s2;
}

// ---------------- CSR build ----------------
__global__ void csr_zero_kernel() {
    int i = blockIdx.x * blockDim.x + threadIdx.x;
    if (i < M_NODES) g_cnt[i] = 0;
}
__global__ void csr_hist_kernel(const int* __restrict__ ei) {
    int idx = blockIdx.x * blockDim.x + threadIdx.x;
    if (idx >= G * NE) return;
    int g = idx / NE, e = idx % NE;
    int dst = ei[(size_t)g * 2 * NE + NE + e];
    atomicAdd(&g_cnt[g * NN + dst], 1);
}
__global__ void csr_scanA_kernel() {
    __shared__ int sh[SCAN_BLK];
    int i = blockIdx.x * SCAN_BLK + threadIdx.x;
    int v = (i < M_NODES) ? g_cnt[i] : 0;
    sh[threadIdx.x] = v;
    __syncthreads();
#pragma unroll
    for (int off = 1; off < SCAN_BLK; off <<= 1) {
        int t = (threadIdx.x >= off) ? sh[threadIdx.x - off] : 0;
        __syncthreads();
        sh[threadIdx.x] += t;
        __syncthreads();
    }
    if (i < M_NODES) g_rowptr[i] = sh[threadIdx.x] - v;
    if (threadIdx.x == SCAN_BLK - 1) g_bsum[blockIdx.x] = sh[SCAN_BLK - 1];
}
__global__ void csr_scanB_kernel() {
    __shared__ int sh[128];
    int t = threadIdx.x;
    int v = (t < NBLK) ? g_bsum[t] : 0;
    sh[t] = v;
    __syncthreads();
#pragma unroll
    for (int off = 1; off < 128; off <<= 1) {
        int u = (t >= off) ? sh[t - off] : 0;
        __syncthreads();
        sh[t] += u;
        __syncthreads();
    }
    if (t < NBLK) g_bpre[t] = sh[t] - v;
    if (t == 127) g_rowptr[M_NODES] = sh[127];
}
__global__ void csr_scanC_kernel() {
    int i = blockIdx.x * blockDim.x + threadIdx.x;
    if (i >= M_NODES) return;
    int v = g_rowptr[i] + g_bpre[i / SCAN_BLK];
    g_rowptr[i] = v;
    g_fill[i] = v;
}
__global__ void csr_scatter_kernel(const int* __restrict__ ei) {
    int idx = blockIdx.x * blockDim.x + threadIdx.x;
    if (idx >= G * NE) return;
    int g = idx / NE, e = idx % NE;
    int src = ei[(size_t)g * 2 * NE + e];
    int dst = ei[(size_t)g * 2 * NE + NE + e];
    int pos = atomicAdd(&g_fill[g * NN + dst], 1);
    g_col[pos] = src;
}

// ---------------- fused online-softmax + aggregation + bias + ELU (warp per dst node) ----------
__device__ __forceinline__ float lrelu(float v) { return v > 0.f ? v : 0.2f * v; }

template <int H, int C, int SPLIT>
__global__ void node_agg_kernel(const float* __restrict__ als, const float* __restrict__ ald,
                                const float* __restrict__ hbuf, const float* __restrict__ bias,
                                float* __restrict__ outf, __nv_bfloat16* __restrict__ ohi,
                                __nv_bfloat16* __restrict__ olo) {
    int wid = (blockIdx.x * blockDim.x + threadIdx.x) >> 5;
    int lane = threadIdx.x & 31;
    if (wid >= M_NODES) return;
    int g = wid / NN;
    const int gbase = g * NN;

    int rbeg = g_rowptr[wid];
    int deg = g_rowptr[wid + 1] - rbeg;

    float aldh[H], m[H], s[H];
#pragma unroll
    for (int h = 0; h < H; h++) {
        aldh[h] = ald[wid * H + h];
        float selfv = lrelu(als[wid * H + h] + aldh[h]);
        m[h] = (lane == 0) ? selfv : -1e30f;
        s[h] = (lane == 0) ? 1.f : 0.f;
    }
    for (int i = lane; i < deg; i += 32) {
        int src = g_col[rbeg + i];
#pragma unroll
        for (int h = 0; h < H; h++) {
            float e = lrelu(als[(gbase + src) * H + h] + aldh[h]);
            float mn = fmaxf(m[h], e);
            s[h] = s[h] * __expf(m[h] - mn) + __expf(e - mn);
            m[h] = mn;
        }
    }
#pragma unroll
    for (int h = 0; h < H; h++) {
#pragma unroll
        for (int off = 16; off > 0; off >>= 1) {
            float mo = __shfl_xor_sync(0xFFFFFFFFu, m[h], off);
            float so = __shfl_xor_sync(0xFFFFFFFFu, s[h], off);
            float mn = fmaxf(m[h], mo);
            s[h] = s[h] * __expf(m[h] - mn) + so * __expf(mo - mn);
            m[h] = mn;
        }
    }

    constexpr int F = H * C;
    constexpr int PER = F / 32;
    const int f0 = lane * PER;
    const int myh = f0 / C;
    const float inv_s = 1.f / s[myh];
    const float mymx = m[myh];
    const float myald = aldh[myh];

    float acc[PER];
    {
        float selfv = lrelu(als[wid * H + myh] + myald);
        float a_self = __expf(selfv - mymx) * inv_s;
        const float* hp = hbuf + (size_t)wid * F + f0;
#pragma unroll
        for (int c = 0; c < PER; c += 4) {
            float4 v = *(const float4*)(hp + c);
            acc[c + 0] = v.x * a_self;
            acc[c + 1] = v.y * a_self;
            acc[c + 2] = v.z * a_self;
            acc[c + 3] = v.w * a_self;
        }
    }
#pragma unroll 2
    for (int i = 0; i < deg; i++) {
        int src = g_col[rbeg + i];
        float alpha = __expf(lrelu(als[(gbase + src) * H + myh] + myald) - mymx) * inv_s;
        const float* hp = hbuf + (size_t)(gbase + src) * F + f0;
#pragma unroll
        for (int c = 0; c < PER; c += 4) {
            float4 v = *(const float4*)(hp + c);
            acc[c + 0] += v.x * alpha;
            acc[c + 1] += v.y * alpha;
            acc[c + 2] += v.z * alpha;
            acc[c + 3] += v.w * alpha;
        }
    }
    const float* bp = bias + g * F + f0;
    if (SPLIT) {
        __nv_bfloat16* hp2 = ohi + (size_t)wid * F + f0;
        __nv_bfloat16* lp2 = olo + (size_t)wid * F + f0;
#pragma unroll
        for (int c = 0; c < PER; c++) {
            float v = acc[c] + bp[c];
            v = v > 0.f ? v : expm1f(v);
            __nv_bfloat16 h = __float2bfloat16(v);
            hp2[c] = h;
            lp2[c] = __float2bfloat16(v - __bfloat162float(h));
        }
    } else {
        float* op = outf + (size_t)wid * F + f0;
#pragma unroll
        for (int c = 0; c < PER; c++) {
            float v = acc[c] + bp[c];
            op[c] = v > 0.f ? v : expm1f(v);
        }
    }
}

// ---------------- host ----------------
static inline int ceil_div(int a, int b) { return (a + b - 1) / b; }

extern "C" void kernel_launch(void* const* d_in, const int* in_sizes, int n_in,
                              void* d_out, int out_size) {
    const float* x   = (const float*)d_in[0];
    const int*   ei  = (const int*)d_in[1];
    const float* W1  = (const float*)d_in[2];
    const float* a1s = (const float*)d_in[3];
    const float* a1d = (const float*)d_in[4];
    const float* b1  = (const float*)d_in[5];
    const float* W2  = (const float*)d_in[6];
    const float* a2s = (const float*)d_in[7];
    const float* a2d = (const float*)d_in[8];
    const float* b2  = (const float*)d_in[9];
    float* out = (float*)d_out;

    float *h1, *h2, *als, *ald;
    __nv_bfloat16 *xhi, *xlo, *a1hi, *a1lo, *w1hi, *w1lo, *w2hi, *w2lo;
    cudaGetSymbolAddress((void**)&h1, g_h1);
    cudaGetSymbolAddress((void**)&h2, g_h2);
    cudaGetSymbolAddress((void**)&als, g_als);
    cudaGetSymbolAddress((void**)&ald, g_ald);
    cudaGetSymbolAddress((void**)&xhi, g_xhi);
    cudaGetSymbolAddress((void**)&xlo, g_xlo);
    cudaGetSymbolAddress((void**)&a1hi, g_a1hi);
    cudaGetSymbolAddress((void**)&a1lo, g_a1lo);
    cudaGetSymbolAddress((void**)&w1hi, g_w1hi);
    cudaGetSymbolAddress((void**)&w1lo, g_w1lo);
    cudaGetSymbolAddress((void**)&w2hi, g_w2hi);
    cudaGetSymbolAddress((void**)&w2lo, g_w2lo);

    cudaFuncSetAttribute(gemm_wmma_kernel<128, 256>,
                         cudaFuncAttributeMaxDynamicSharedMemorySize, SMEM_TOT);
    cudaFuncSetAttribute(gemm_wmma_kernel<256, 128>,
                         cudaFuncAttributeMaxDynamicSharedMemorySize, SMEM_TOT);

    const int TPB = 256;
    const int nrow_blocks = ceil_div(NN, 128);  // 391

    // conversions first, gemm1 as the 4th launch (ncu capture window)
    split_kernel<<<ceil_div(G * NN * 128 / 4, TPB), TPB>>>(x, xhi, xlo, G * NN * 128 / 4);
    split_kernel<<<ceil_div(G * 128 * 256 / 4, TPB), TPB>>>(W1, w1hi, w1lo, G * 128 * 256 / 4);
    split_kernel<<<ceil_div(G * 256 * 128 / 4, TPB), TPB>>>(W2, w2hi, w2lo, G * 256 * 128 / 4);
    gemm_wmma_kernel<128, 256><<<dim3(nrow_blocks, 2, G), TPB, SMEM_TOT>>>(xhi, xlo, w1hi, w1lo, h1);

    // CSR build (shared by both layers)
    csr_zero_kernel<<<ceil_div(M_NODES, TPB), TPB>>>();
    csr_hist_kernel<<<ceil_div(G * NE, TPB), TPB>>>(ei);
    csr_scanA_kernel<<<NBLK, SCAN_BLK>>>();
    csr_scanB_kernel<<<1, 128>>>();
    csr_scanC_kernel<<<ceil_div(M_NODES, TPB), TPB>>>();
    csr_scatter_kernel<<<ceil_div(G * NE, TPB), TPB>>>(ei);

    // ---- Layer 1: heads=4, C=64 ----
    al_kernel<4, 64><<<ceil_div(G * NN * 4, TPB), TPB>>>(h1, a1s, a1d, als, ald);
    node_agg_kernel<4, 64, 1><<<ceil_div(M_NODES * 32, TPB), TPB>>>(als, ald, h1, b1,
                                                                    (float*)0, a1hi, a1lo);

    // ---- Layer 2: heads=1, C=128 ----
    gemm_wmma_kernel<256, 128><<<dim3(nrow_blocks, 1, G), TPB, SMEM_TOT>>>(a1hi, a1lo, w2hi, w2lo, h2);
    al_kernel<1, 128><<<ceil_div(G * NN, TPB), TPB>>>(h2, a2s, a2d, als, ald);
    node_agg_kernel<1, 128, 0><<<ceil_div(M_NODES * 32, TPB), TPB>>>(als, ald, h2, b2,
                                                                     out, (__nv_bfloat16*)0,
                                                                     (__nv_bfloat16*)0);
}